// round 11
// baseline (speedup 1.0000x reference)
#include <cuda_runtime.h>
#include <cuda_fp16.h>
#include <cuda_bf16.h>

// SSIM fused single-kernel, tensor-core separable conv, register-resident
// intermediate (movmatrix instead of smem round-trip).
// X,Y: [64,1,320,320] f32; window [1,1,7,7] rank-1 Gaussian. out = 1 - mean(ssim).
//
// Phase 1: stage centered fp16 planes x', y' as [38 rows][72 cols] in smem.
// Phase 2+3 fused per warp (warp j owns output cols 8j..8j+7):
//   - For row-blocks m0 in {0,16,22}: ldmatrix x,y A-frags, build z=x'^2+y'^2 and
//     p=x'y' frags in registers, horizontal mma vs constant T0[a][b]=w[a-b-1],
//     cvt f32->half2 and movmatrix.trans -> vertical B-fragment tiles (in regs).
//   - Vertical mma: rows 0-15 = F0*tiles(0) + F1*tiles(16);
//                   rows 16-31 = F0*tiles(16) + G*tiles(22) (G masks k<10).
//   - SSIM elementwise on D fragments (all 4 streams share layout).

typedef unsigned int u32;

#define IMG_H 320
#define IMG_W 320
#define N_IMG 64
#define TILE_W 64
#define TILE_H 32
#define IN_R 38
#define S_ST 72              // halfs per row = 144B = 9 x 16B (odd) -> ldmatrix conflict-free
#define GRID_X (IMG_W / TILE_W)   // 5
#define GRID_Y (IMG_H / TILE_H)   // 10
#define NBLOCKS (GRID_X * GRID_Y * N_IMG)   // 3200

#define C1_CONST 0.0004f
#define C2_CONST 0.0036f
#define COV_NORM_CONST (49.0f / 48.0f)

__device__ float g_part[NBLOCKS];
__device__ unsigned g_ticket;   // atomicInc wraps to 0 -> graph-replay safe

__device__ __forceinline__ u32 h2u(__half2 h) { return *reinterpret_cast<u32*>(&h); }
__device__ __forceinline__ __half2 u2h(u32 u) { return *reinterpret_cast<__half2*>(&u); }

__device__ __forceinline__ void ldsm_x4(u32 a, u32& r0, u32& r1, u32& r2, u32& r3) {
    asm volatile("ldmatrix.sync.aligned.m8n8.x4.shared.b16 {%0,%1,%2,%3}, [%4];"
                 : "=r"(r0), "=r"(r1), "=r"(r2), "=r"(r3) : "r"(a));
}
__device__ __forceinline__ void ldsm_x2t(u32 a, u32& r0, u32& r1) {
    asm volatile("ldmatrix.sync.aligned.m8n8.x2.trans.shared.b16 {%0,%1}, [%2];"
                 : "=r"(r0), "=r"(r1) : "r"(a));
}
__device__ __forceinline__ u32 movm_t(u32 a) {
    u32 d;
    asm volatile("movmatrix.sync.aligned.m8n8.trans.b16 %0, %1;" : "=r"(d) : "r"(a));
    return d;
}
__device__ __forceinline__ void mma_16816(float d[4], const u32 a[4], const u32 b[2],
                                          const float c[4]) {
    asm volatile("mma.sync.aligned.m16n8k16.row.col.f32.f16.f16.f32 "
                 "{%0,%1,%2,%3}, {%4,%5,%6,%7}, {%8,%9}, {%10,%11,%12,%13};"
                 : "=f"(d[0]), "=f"(d[1]), "=f"(d[2]), "=f"(d[3])
                 : "r"(a[0]), "r"(a[1]), "r"(a[2]), "r"(a[3]),
                   "r"(b[0]), "r"(b[1]),
                   "f"(c[0]), "f"(c[1]), "f"(c[2]), "f"(c[3]));
}

__global__ __launch_bounds__(256, 4)
void ssim_kernel(const float* __restrict__ X, const float* __restrict__ Y,
                 const float* __restrict__ W, float* __restrict__ out) {
    __shared__ __half sS[2][IN_R * S_ST];   // staging: x', y'
    __shared__ __half F0m[256], F1m[256], Gm[256], T0m[128];
    __shared__ float warp_sums[8];
    __shared__ int is_last;

    const int tid  = threadIdx.x;
    const int lane = tid & 31;
    const int wid  = tid >> 5;
    const int bx = blockIdx.x * TILE_W;
    const int by = blockIdx.y * TILE_H;
    const int n  = blockIdx.z;

    // ---- Constant Toeplitz matrices from the rank-1 window ----
    const float wc = sqrtf(W[3 * 7 + 3]);
    {
        auto wv = [&](int d) -> __half {
            return (d >= 0 && d <= 6) ? __float2half(W[d * 7 + 3] / wc)
                                      : __float2half(0.0f);
        };
        int m = tid >> 4, k = tid & 15;
        F0m[tid] = wv(k - m);
        F1m[tid] = wv(16 + k - m);
        Gm[tid]  = (k >= 10) ? wv(6 + k - m) : __float2half(0.0f);
        if (tid < 128) { int a = tid >> 3, b = tid & 7; T0m[tid] = wv(a - b - 1); }
    }

    const float* Xn = X + (size_t)n * IMG_H * IMG_W;
    const float* Yn = Y + (size_t)n * IMG_H * IMG_W;

    // ---- Phase 1: stage 38 rows x 72 cols (orig cols bx-4 .. bx+67), centered ----
    for (int t = tid; t < IN_R * 18; t += 256) {
        int r = t / 18, g = t - r * 18;
        int gy = by + r - 3;
        int c0 = bx - 4 + 4 * g;
        float4 xv = make_float4(0.f, 0.f, 0.f, 0.f);
        float4 yv = make_float4(0.f, 0.f, 0.f, 0.f);
        if ((unsigned)gy < (unsigned)IMG_H && (unsigned)c0 < (unsigned)IMG_W) {
            xv = *(const float4*)(Xn + gy * IMG_W + c0);
            yv = *(const float4*)(Yn + gy * IMG_W + c0);
        }
        __half2 x01 = __floats2half2_rn(xv.x - 0.5f, xv.y - 0.5f);
        __half2 x23 = __floats2half2_rn(xv.z - 0.5f, xv.w - 0.5f);
        __half2 y01 = __floats2half2_rn(yv.x - 0.5f, yv.y - 0.5f);
        __half2 y23 = __floats2half2_rn(yv.z - 0.5f, yv.w - 0.5f);
        int o = r * S_ST + 4 * g;
        *(uint2*)&sS[0][o] = make_uint2(h2u(x01), h2u(x23));
        *(uint2*)&sS[1][o] = make_uint2(h2u(y01), h2u(y23));
    }
    __syncthreads();

    // ---- Constant fragments (per warp) ----
    const int arow = (lane & 7) + (((lane >> 3) & 1) << 3);   // 0..15
    const int acol = (lane & 16) >> 1;                        // 0 or 8
    u32 f0[4], f1[4], gm[4], t0[2];
    ldsm_x4((u32)__cvta_generic_to_shared(&F0m[arow * 16 + acol]), f0[0], f0[1], f0[2], f0[3]);
    ldsm_x4((u32)__cvta_generic_to_shared(&F1m[arow * 16 + acol]), f1[0], f1[1], f1[2], f1[3]);
    ldsm_x4((u32)__cvta_generic_to_shared(&Gm [arow * 16 + acol]), gm[0], gm[1], gm[2], gm[3]);
    ldsm_x2t((u32)__cvta_generic_to_shared(&T0m[(lane & 15) * 8]), t0[0], t0[1]);

    // ---- Fused horizontal conv -> register tiles (movmatrix) -> vertical conv ----
    const int j = wid;   // n-block: output cols 8j..8j+7
    u32 tiles[3][4][2];  // [row-block 0/16/22][stream][lo(k0-7)/hi(k8-15)] B-frag tiles

    #pragma unroll
    for (int bkt = 0; bkt < 3; bkt++) {
        const int m0 = (bkt == 0) ? 0 : (bkt == 1) ? 16 : 22;
        u32 ax[4], ay[4], az[4], ap[4];
        ldsm_x4((u32)__cvta_generic_to_shared(
                    &sS[0][(m0 + arow) * S_ST + 8 * j + acol]),
                ax[0], ax[1], ax[2], ax[3]);
        ldsm_x4((u32)__cvta_generic_to_shared(
                    &sS[1][(m0 + arow) * S_ST + 8 * j + acol]),
                ay[0], ay[1], ay[2], ay[3]);
        #pragma unroll
        for (int q = 0; q < 4; q++) {
            __half2 xh = u2h(ax[q]), yh = u2h(ay[q]);
            az[q] = h2u(__hfma2(xh, xh, __hmul2(yh, yh)));
            ap[q] = h2u(__hmul2(xh, yh));
        }
        #pragma unroll
        for (int s = 0; s < 4; s++) {
            const u32* a = (s == 0) ? ax : (s == 1) ? ay : (s == 2) ? az : ap;
            float d[4] = {0.f, 0.f, 0.f, 0.f};
            mma_16816(d, a, t0, d);
            // accum-layout tiles (rows m0..m0+7 and m0+8..m0+15) -> B-frag via trans
            tiles[bkt][s][0] = movm_t(h2u(__floats2half2_rn(d[0], d[1])));
            tiles[bkt][s][1] = movm_t(h2u(__floats2half2_rn(d[2], d[3])));
        }
    }

    float facc = 0.f;
    #pragma unroll
    for (int i = 0; i < 2; i++) {
        float D[4][4];
        #pragma unroll
        for (int s = 0; s < 4; s++) {
            float d[4] = {0.f, 0.f, 0.f, 0.f};
            if (i == 0) {
                mma_16816(d, f0, tiles[0][s], d);
                mma_16816(d, f1, tiles[1][s], d);
            } else {
                mma_16816(d, f0, tiles[1][s], d);
                mma_16816(d, gm, tiles[2][s], d);
            }
            D[s][0] = d[0]; D[s][1] = d[1]; D[s][2] = d[2]; D[s][3] = d[3];
        }
        #pragma unroll
        for (int e = 0; e < 4; e++) {
            float muxc = D[0][e], muyc = D[1][e];
            float s23c = D[2][e], spc  = D[3][e];
            float Pc   = fmaf(muxc, muxc, muyc * muyc);
            float ssum = (s23c - Pc)          * COV_NORM_CONST;
            float sxy  = (spc  - muxc * muyc) * COV_NORM_CONST;
            float mux = muxc + 0.5f;
            float muy = muyc + 0.5f;
            float muxy = mux * muy;
            float P    = fmaf(mux, mux, muy * muy);
            float num = fmaf(2.f, muxy, C1_CONST) * fmaf(2.f, sxy, C2_CONST);
            float den = (P + C1_CONST) * (ssum + C2_CONST);
            facc += __fdividef(num, den);
        }
    }

    // ---- Block reduction -> per-block float partial ----
    #pragma unroll
    for (int off = 16; off > 0; off >>= 1)
        facc += __shfl_down_sync(0xffffffffu, facc, off);
    if (lane == 0) warp_sums[wid] = facc;
    __syncthreads();
    if (tid == 0) {
        float bs = 0.f;
        #pragma unroll
        for (int w = 0; w < 8; w++) bs += warp_sums[w];
        int bid = blockIdx.x + GRID_X * (blockIdx.y + GRID_Y * blockIdx.z);
        g_part[bid] = bs;
        __threadfence();
        unsigned ticket = atomicInc(&g_ticket, NBLOCKS - 1);
        is_last = (ticket == NBLOCKS - 1);
    }
    __syncthreads();

    // ---- Last block: deterministic double reduction ----
    if (is_last) {
        __shared__ double dsums[8];
        double s = 0.0;
        for (int i = tid; i < NBLOCKS; i += 256) s += (double)__ldcg(&g_part[i]);
        #pragma unroll
        for (int off = 16; off > 0; off >>= 1)
            s += __shfl_down_sync(0xffffffffu, s, off);
        if (lane == 0) dsums[wid] = s;
        __syncthreads();
        if (tid == 0) {
            double t = 0.0;
            #pragma unroll
            for (int w = 0; w < 8; w++) t += dsums[w];
            double total = (double)N_IMG * IMG_H * IMG_W;
            out[0] = (float)(1.0 - t / total);
        }
    }
}

extern "C" void kernel_launch(void* const* d_in, const int* in_sizes, int n_in,
                              void* d_out, int out_size) {
    const float* X = (const float*)d_in[0];
    const float* Y = (const float*)d_in[1];
    const float* W = (const float*)d_in[2];
    float* out = (float*)d_out;

    dim3 grid(GRID_X, GRID_Y, N_IMG);
    ssim_kernel<<<grid, 256>>>(X, Y, W, out);
}

// round 12
// speedup vs baseline: 1.3019x; 1.3019x over previous
#include <cuda_runtime.h>
#include <cuda_fp16.h>
#include <cuda_bf16.h>

// SSIM fused single-kernel, tensor-core separable conv, register-resident
// intermediates (movmatrix), sliding row-block pipeline over a 64x64 tile.
// X,Y: [64,1,320,320] f32; window [1,1,7,7] rank-1 Gaussian. out = 1 - mean(ssim).
//
// Phase 1: stage centered fp16 planes x', y' as [70 rows][72 cols] in smem.
// Per warp (warp j owns output cols 8j..8j+7):
//   compute_h(m0): ldmatrix x,y A-frags at rows m0..m0+15, build z=x'^2+y'^2,
//   p=x'y' in registers, horizontal mma vs constant T0[a][b]=w[a-b-1],
//   cvt+movmatrix -> vertical B-fragment tile set (4 streams x 2).
//   Sliding steps s=0..3: out rows 16s..16s+15 = F0*H(16s) + F1*H(16s+16)
//   (s=3: F0*H(48) + G*H(54), G masks k<10). SSIM elementwise on D fragments.

typedef unsigned int u32;

#define IMG_H 320
#define IMG_W 320
#define N_IMG 64
#define TILE_W 64
#define TILE_H 64
#define IN_R 70              // TILE_H + 6
#define S_ST 72              // halfs per row = 144B = 9 x 16B (odd) -> ldmatrix conflict-free
#define GRID_X (IMG_W / TILE_W)   // 5
#define GRID_Y (IMG_H / TILE_H)   // 5
#define NBLOCKS (GRID_X * GRID_Y * N_IMG)   // 1600

#define C1_CONST 0.0004f
#define C2_CONST 0.0036f
#define COV_NORM_CONST (49.0f / 48.0f)

__device__ float g_part[NBLOCKS];
__device__ unsigned g_ticket;   // atomicInc wraps to 0 -> graph-replay safe

__device__ __forceinline__ u32 h2u(__half2 h) { return *reinterpret_cast<u32*>(&h); }
__device__ __forceinline__ __half2 u2h(u32 u) { return *reinterpret_cast<__half2*>(&u); }

__device__ __forceinline__ void ldsm_x4(u32 a, u32& r0, u32& r1, u32& r2, u32& r3) {
    asm volatile("ldmatrix.sync.aligned.m8n8.x4.shared.b16 {%0,%1,%2,%3}, [%4];"
                 : "=r"(r0), "=r"(r1), "=r"(r2), "=r"(r3) : "r"(a));
}
__device__ __forceinline__ void ldsm_x2t(u32 a, u32& r0, u32& r1) {
    asm volatile("ldmatrix.sync.aligned.m8n8.x2.trans.shared.b16 {%0,%1}, [%2];"
                 : "=r"(r0), "=r"(r1) : "r"(a));
}
__device__ __forceinline__ u32 movm_t(u32 a) {
    u32 d;
    asm volatile("movmatrix.sync.aligned.m8n8.trans.b16 %0, %1;" : "=r"(d) : "r"(a));
    return d;
}
__device__ __forceinline__ void mma_16816(float d[4], const u32 a[4], const u32 b[2],
                                          const float c[4]) {
    asm volatile("mma.sync.aligned.m16n8k16.row.col.f32.f16.f16.f32 "
                 "{%0,%1,%2,%3}, {%4,%5,%6,%7}, {%8,%9}, {%10,%11,%12,%13};"
                 : "=f"(d[0]), "=f"(d[1]), "=f"(d[2]), "=f"(d[3])
                 : "r"(a[0]), "r"(a[1]), "r"(a[2]), "r"(a[3]),
                   "r"(b[0]), "r"(b[1]),
                   "f"(c[0]), "f"(c[1]), "f"(c[2]), "f"(c[3]));
}

__global__ __launch_bounds__(256, 4)
void ssim_kernel(const float* __restrict__ X, const float* __restrict__ Y,
                 const float* __restrict__ W, float* __restrict__ out) {
    __shared__ __half sS[2][IN_R * S_ST];   // staging: x', y'  (~19.7 KB)
    __shared__ __half F0m[256], F1m[256], Gm[256], T0m[128];
    __shared__ float warp_sums[8];
    __shared__ int is_last;

    const int tid  = threadIdx.x;
    const int lane = tid & 31;
    const int wid  = tid >> 5;
    const int bx = blockIdx.x * TILE_W;
    const int by = blockIdx.y * TILE_H;
    const int n  = blockIdx.z;

    // ---- Constant Toeplitz matrices from the rank-1 window ----
    const float wc = sqrtf(W[3 * 7 + 3]);
    {
        auto wv = [&](int d) -> __half {
            return (d >= 0 && d <= 6) ? __float2half(W[d * 7 + 3] / wc)
                                      : __float2half(0.0f);
        };
        int m = tid >> 4, k = tid & 15;
        F0m[tid] = wv(k - m);
        F1m[tid] = wv(16 + k - m);
        Gm[tid]  = (k >= 10) ? wv(6 + k - m) : __float2half(0.0f);
        if (tid < 128) { int a = tid >> 3, b = tid & 7; T0m[tid] = wv(a - b - 1); }
    }

    const float* Xn = X + (size_t)n * IMG_H * IMG_W;
    const float* Yn = Y + (size_t)n * IMG_H * IMG_W;

    // ---- Phase 1: stage 70 rows x 72 cols (orig cols bx-4 .. bx+67), centered ----
    for (int t = tid; t < IN_R * 18; t += 256) {
        int r = t / 18, g = t - r * 18;
        int gy = by + r - 3;
        int c0 = bx - 4 + 4 * g;
        float4 xv = make_float4(0.f, 0.f, 0.f, 0.f);
        float4 yv = make_float4(0.f, 0.f, 0.f, 0.f);
        if ((unsigned)gy < (unsigned)IMG_H && (unsigned)c0 < (unsigned)IMG_W) {
            xv = *(const float4*)(Xn + gy * IMG_W + c0);
            yv = *(const float4*)(Yn + gy * IMG_W + c0);
        }
        __half2 x01 = __floats2half2_rn(xv.x - 0.5f, xv.y - 0.5f);
        __half2 x23 = __floats2half2_rn(xv.z - 0.5f, xv.w - 0.5f);
        __half2 y01 = __floats2half2_rn(yv.x - 0.5f, yv.y - 0.5f);
        __half2 y23 = __floats2half2_rn(yv.z - 0.5f, yv.w - 0.5f);
        int o = r * S_ST + 4 * g;
        *(uint2*)&sS[0][o] = make_uint2(h2u(x01), h2u(x23));
        *(uint2*)&sS[1][o] = make_uint2(h2u(y01), h2u(y23));
    }
    __syncthreads();

    // ---- Constant fragments (per warp) ----
    const int arow = (lane & 7) + (((lane >> 3) & 1) << 3);   // 0..15
    const int acol = (lane & 16) >> 1;                        // 0 or 8
    u32 f0[4], f1[4], gm[4], t0[2];
    ldsm_x4((u32)__cvta_generic_to_shared(&F0m[arow * 16 + acol]), f0[0], f0[1], f0[2], f0[3]);
    ldsm_x4((u32)__cvta_generic_to_shared(&F1m[arow * 16 + acol]), f1[0], f1[1], f1[2], f1[3]);
    ldsm_x4((u32)__cvta_generic_to_shared(&Gm [arow * 16 + acol]), gm[0], gm[1], gm[2], gm[3]);
    ldsm_x2t((u32)__cvta_generic_to_shared(&T0m[(lane & 15) * 8]), t0[0], t0[1]);

    const int j = wid;   // n-block: output cols 8j..8j+7

    // horizontal conv of rows m0..m0+15 -> B-fragment tile set (4 streams x 2)
    auto compute_h = [&](int m0, u32 tiles[4][2]) {
        u32 ax[4], ay[4], az[4], ap[4];
        ldsm_x4((u32)__cvta_generic_to_shared(
                    &sS[0][(m0 + arow) * S_ST + 8 * j + acol]),
                ax[0], ax[1], ax[2], ax[3]);
        ldsm_x4((u32)__cvta_generic_to_shared(
                    &sS[1][(m0 + arow) * S_ST + 8 * j + acol]),
                ay[0], ay[1], ay[2], ay[3]);
        #pragma unroll
        for (int q = 0; q < 4; q++) {
            __half2 xh = u2h(ax[q]), yh = u2h(ay[q]);
            az[q] = h2u(__hfma2(xh, xh, __hmul2(yh, yh)));
            ap[q] = h2u(__hmul2(xh, yh));
        }
        #pragma unroll
        for (int s = 0; s < 4; s++) {
            const u32* a = (s == 0) ? ax : (s == 1) ? ay : (s == 2) ? az : ap;
            float d[4] = {0.f, 0.f, 0.f, 0.f};
            mma_16816(d, a, t0, d);
            tiles[s][0] = movm_t(h2u(__floats2half2_rn(d[0], d[1])));
            tiles[s][1] = movm_t(h2u(__floats2half2_rn(d[2], d[3])));
        }
    };

    // ---- Sliding pipeline over 4 output row-blocks ----
    float facc = 0.f;
    u32 tA[4][2], tB[4][2];
    compute_h(0, tA);
    #pragma unroll
    for (int step = 0; step < 4; step++) {
        const int m_next = (step < 3) ? 16 * (step + 1) : 54;
        compute_h(m_next, tB);

        float Darr[4][4];
        #pragma unroll
        for (int s = 0; s < 4; s++) {
            float d[4] = {0.f, 0.f, 0.f, 0.f};
            mma_16816(d, f0, tA[s], d);
            if (step < 3) mma_16816(d, f1, tB[s], d);
            else          mma_16816(d, gm, tB[s], d);
            Darr[s][0] = d[0]; Darr[s][1] = d[1];
            Darr[s][2] = d[2]; Darr[s][3] = d[3];
        }
        #pragma unroll
        for (int e = 0; e < 4; e++) {
            float muxc = Darr[0][e], muyc = Darr[1][e];
            float s23c = Darr[2][e], spc  = Darr[3][e];
            float Pc   = fmaf(muxc, muxc, muyc * muyc);
            float ssum = (s23c - Pc)          * COV_NORM_CONST;
            float sxy  = (spc  - muxc * muyc) * COV_NORM_CONST;
            float mux = muxc + 0.5f;
            float muy = muyc + 0.5f;
            float muxy = mux * muy;
            float P    = fmaf(mux, mux, muy * muy);
            float num = fmaf(2.f, muxy, C1_CONST) * fmaf(2.f, sxy, C2_CONST);
            float den = (P + C1_CONST) * (ssum + C2_CONST);
            facc += __fdividef(num, den);
        }
        // rotate: tB -> tA
        #pragma unroll
        for (int s = 0; s < 4; s++) {
            tA[s][0] = tB[s][0];
            tA[s][1] = tB[s][1];
        }
    }

    // ---- Block reduction -> per-block float partial ----
    #pragma unroll
    for (int off = 16; off > 0; off >>= 1)
        facc += __shfl_down_sync(0xffffffffu, facc, off);
    if (lane == 0) warp_sums[wid] = facc;
    __syncthreads();
    if (tid == 0) {
        float bs = 0.f;
        #pragma unroll
        for (int w = 0; w < 8; w++) bs += warp_sums[w];
        int bid = blockIdx.x + GRID_X * (blockIdx.y + GRID_Y * blockIdx.z);
        g_part[bid] = bs;
        __threadfence();
        unsigned ticket = atomicInc(&g_ticket, NBLOCKS - 1);
        is_last = (ticket == NBLOCKS - 1);
    }
    __syncthreads();

    // ---- Last block: deterministic double reduction ----
    if (is_last) {
        __shared__ double dsums[8];
        double s = 0.0;
        for (int i = tid; i < NBLOCKS; i += 256) s += (double)__ldcg(&g_part[i]);
        #pragma unroll
        for (int off = 16; off > 0; off >>= 1)
            s += __shfl_down_sync(0xffffffffu, s, off);
        if (lane == 0) dsums[wid] = s;
        __syncthreads();
        if (tid == 0) {
            double t = 0.0;
            #pragma unroll
            for (int w = 0; w < 8; w++) t += dsums[w];
            double total = (double)N_IMG * IMG_H * IMG_W;
            out[0] = (float)(1.0 - t / total);
        }
    }
}

extern "C" void kernel_launch(void* const* d_in, const int* in_sizes, int n_in,
                              void* d_out, int out_size) {
    const float* X = (const float*)d_in[0];
    const float* Y = (const float*)d_in[1];
    const float* W = (const float*)d_in[2];
    float* out = (float*)d_out;

    dim3 grid(GRID_X, GRID_Y, N_IMG);
    ssim_kernel<<<grid, 256>>>(X, Y, W, out);
}